// round 1
// baseline (speedup 1.0000x reference)
#include <cuda_runtime.h>

#define N_STEPS 2048
#define N_ARMS  5000
#define HS      10
#define NPOW    11   // 2^11 = 2048

// Scratch (allocation-free rule: __device__ globals)
__device__ float g_pow[NPOW][HS][HS];   // M^(2^k)
__device__ float g_x0[HS];
__device__ __align__(16) float g_actions[N_STEPS * 2];  // pre-scaled by 15000

// ---------------------------------------------------------------------------
// Kernel A: single block. MLP -> x0, Gauss-Jordan inv(P), A, M, powers of M.
// ---------------------------------------------------------------------------
__global__ void setup_kernel(const float* __restrict__ target,
                             const float* __restrict__ D,
                             const float* __restrict__ P,
                             const float* __restrict__ W1,
                             const float* __restrict__ b1,
                             const float* __restrict__ W2,
                             const float* __restrict__ b2) {
    __shared__ float h[256];
    __shared__ float B[HS][2 * HS];    // augmented [P | I] -> [I | Pinv]
    __shared__ float ps[HS][16];
    __shared__ float x0s[HS];
    __shared__ float f[HS];
    __shared__ float expD[HS];
    __shared__ float Psh[HS][HS];
    __shared__ float Pk[HS][HS];
    __shared__ float Pn[HS][HS];
    __shared__ int   sPiv;
    __shared__ float sPivInv;

    const int tid = threadIdx.x;
    const float t0 = target[0], t1 = target[1];

    // h = relu(W1 @ target + b1), one output per thread
    h[tid] = fmaxf(fmaf(W1[2 * tid], t0, fmaf(W1[2 * tid + 1], t1, b1[tid])), 0.0f);

    // Independent small loads
    if (tid < 10)  expD[tid] = expf(D[tid]);
    if (tid < 100) Psh[tid / 10][tid % 10] = P[tid];
    if (tid < 200) {
        int r = tid / 20, c = tid % 20;
        B[r][c] = (c < 10) ? P[r * 10 + c] : ((c - 10) == r ? 1.0f : 0.0f);
    }
    __syncthreads();

    // x0 = W2 @ h + b2 : 10 outputs x 16 partial lanes
    if (tid < 160) {
        int o = tid >> 4, l = tid & 15;
        float s = 0.0f;
        #pragma unroll
        for (int j = 0; j < 16; j++)
            s = fmaf(W2[o * 256 + (l + 16 * j)], h[l + 16 * j], s);
        ps[o][l] = s;
    }
    __syncthreads();
    if (tid < 10) {
        float s = b2[tid];
        #pragma unroll
        for (int l = 0; l < 16; l++) s += ps[tid][l];
        x0s[tid] = s;
    }

    // Gauss-Jordan with partial pivoting on B = [P | I]
    for (int k = 0; k < 10; k++) {
        if (tid == 0) {
            int p = k; float best = fabsf(B[k][k]);
            for (int r = k + 1; r < 10; r++) {
                float v = fabsf(B[r][k]);
                if (v > best) { best = v; p = r; }
            }
            sPiv = p;
        }
        __syncthreads();
        const int p = sPiv;
        if (p != k && tid < 20) {
            float tmp = B[k][tid]; B[k][tid] = B[p][tid]; B[p][tid] = tmp;
        }
        __syncthreads();
        if (tid == 0) sPivInv = 1.0f / B[k][k];
        __syncthreads();
        if (tid < 20) B[k][tid] *= sPivInv;
        __syncthreads();
        if (tid == 0) B[k][k] = 1.0f;
        if (tid < 10 && tid != k) f[tid] = B[tid][k];
        __syncthreads();
        if (tid < 200) {
            int r = tid / 20, c = tid % 20;
            if (r != k) B[r][c] = fmaf(-f[r], B[k][c], B[r][c]);
        }
        __syncthreads();
    }

    // A[i][j] = sum_k P[i][k]*expD[k]*Pinv[k][j];  M = I - 0.01*A
    if (tid < 100) {
        int i = tid / 10, j = tid % 10;
        float a = 0.0f;
        #pragma unroll
        for (int k = 0; k < 10; k++)
            a = fmaf(Psh[i][k] * expD[k], B[k][10 + j], a);
        float m = ((i == j) ? 1.0f : 0.0f) - 0.01f * a;
        Pk[i][j] = m;
        g_pow[0][i][j] = m;
    }
    __syncthreads();

    // Repeated squaring: g_pow[k] = M^(2^k)
    for (int k = 1; k < NPOW; k++) {
        if (tid < 100) {
            int i = tid / 10, j = tid % 10;
            float a = 0.0f;
            #pragma unroll
            for (int q = 0; q < 10; q++)
                a = fmaf(Pk[i][q], Pk[q][j], a);
            Pn[i][j] = a;
        }
        __syncthreads();
        if (tid < 100) {
            int i = tid / 10, j = tid % 10;
            Pk[i][j] = Pn[i][j];
            g_pow[k][i][j] = Pn[i][j];
        }
        __syncthreads();
    }

    if (tid < 10) g_x0[tid] = x0s[tid];
}

// ---------------------------------------------------------------------------
// Kernel B: 2048 threads, one per timestep t.
// hidden[t] = M^t x0 via binary decomposition of t; actions = tanh(...)*15000
// ---------------------------------------------------------------------------
__global__ void rollout_kernel(const float* __restrict__ Wm,
                               const float* __restrict__ bm) {
    __shared__ float powS[NPOW][HS][HS];
    __shared__ float x0S[HS];
    __shared__ float WmS[2][HS];
    __shared__ float bmS[2];

    const int tid = threadIdx.x;
    for (int i = tid; i < NPOW * HS * HS; i += blockDim.x)
        (&powS[0][0][0])[i] = (&g_pow[0][0][0])[i];
    if (tid < 10) x0S[tid] = g_x0[tid];
    if (tid < 20) (&WmS[0][0])[tid] = Wm[tid];
    if (tid < 2)  bmS[tid] = bm[tid];
    __syncthreads();

    const int t = blockIdx.x * blockDim.x + tid;  // 0..2047

    float x[HS];
    #pragma unroll
    for (int i = 0; i < HS; i++) x[i] = x0S[i];

    #pragma unroll
    for (int k = 0; k < NPOW; k++) {
        if ((t >> k) & 1) {
            float y[HS];
            #pragma unroll
            for (int i = 0; i < HS; i++) {
                float s = 0.0f;
                #pragma unroll
                for (int j = 0; j < HS; j++)
                    s = fmaf(powS[k][i][j], x[j], s);
                y[i] = s;
            }
            #pragma unroll
            for (int i = 0; i < HS; i++) x[i] = y[i];
        }
    }

    float a0 = bmS[0], a1 = bmS[1];
    #pragma unroll
    for (int j = 0; j < HS; j++) {
        a0 = fmaf(WmS[0][j], x[j], a0);
        a1 = fmaf(WmS[1][j], x[j], a1);
    }
    g_actions[2 * t]     = tanhf(a0) * 15000.0f;
    g_actions[2 * t + 1] = tanhf(a1) * 15000.0f;
}

// ---------------------------------------------------------------------------
// Kernel C: streaming. out[g] = actions_scaled[g & 4095] + 150*eps[g]
// float4-vectorized; actions staged in shared (4096 floats = 1024 float4).
// ---------------------------------------------------------------------------
__global__ void stream_kernel(const float4* __restrict__ eps4,
                              float4* __restrict__ out4,
                              int n4) {
    __shared__ float4 actS[1024];
    const int tid = threadIdx.x;
    const float4* act4 = reinterpret_cast<const float4*>(g_actions);
    for (int i = tid; i < 1024; i += blockDim.x) actS[i] = act4[i];
    __syncthreads();

    const int stride = gridDim.x * blockDim.x;
    for (int i = blockIdx.x * blockDim.x + tid; i < n4; i += stride) {
        float4 e = eps4[i];
        float4 a = actS[i & 1023];
        float4 o;
        o.x = fmaf(150.0f, e.x, a.x);
        o.y = fmaf(150.0f, e.y, a.y);
        o.z = fmaf(150.0f, e.z, a.z);
        o.w = fmaf(150.0f, e.w, a.w);
        out4[i] = o;
    }
}

// ---------------------------------------------------------------------------
extern "C" void kernel_launch(void* const* d_in, const int* in_sizes, int n_in,
                              void* d_out, int out_size) {
    const float* target = (const float*)d_in[0];
    const float* eps    = (const float*)d_in[1];
    const float* D      = (const float*)d_in[2];
    const float* P      = (const float*)d_in[3];
    const float* W1     = (const float*)d_in[4];
    const float* b1     = (const float*)d_in[5];
    const float* W2     = (const float*)d_in[6];
    const float* b2     = (const float*)d_in[7];
    const float* Wm     = (const float*)d_in[8];
    const float* bm     = (const float*)d_in[9];

    setup_kernel<<<1, 256>>>(target, D, P, W1, b1, W2, b2);
    rollout_kernel<<<N_STEPS / 256, 256>>>(Wm, bm);

    const int n4 = out_size / 4;  // 5,120,000 float4
    stream_kernel<<<1184, 256>>>((const float4*)eps, (float4*)d_out, n4);
}

// round 3
// speedup vs baseline: 1.0447x; 1.0447x over previous
#include <cuda_runtime.h>

#define N_STEPS 2048
#define N_ARMS  5000
#define HS      10
#define NPOW    11   // 2^11 = 2048

// Scratch (allocation-free rule: __device__ globals)
__device__ __align__(16) float g_actions[N_STEPS * 2];  // pre-scaled by 15000

// ---------------------------------------------------------------------------
// Kernel 1: fused setup + rollout.  Grid = 8 blocks x 256 threads.
// Every block redundantly computes the full setup (fully parallel across
// blocks); the serial Gauss-Jordan + repeated-squaring chain runs
// warp-synchronously in warp 0 only (shuffle reductions, __syncwarp, zero
// block barriers inside the serial loops). Then each thread computes
// hidden[t] = M^t x0 via binary decomposition and the tanh head.
// ---------------------------------------------------------------------------
__global__ void __launch_bounds__(256)
prep_kernel(const float* __restrict__ target,
            const float* __restrict__ D,
            const float* __restrict__ P,
            const float* __restrict__ W1,
            const float* __restrict__ b1,
            const float* __restrict__ W2,
            const float* __restrict__ b2,
            const float* __restrict__ Wm,
            const float* __restrict__ bm) {
    __shared__ float h[256];
    __shared__ float ps[HS][16];
    __shared__ float B[HS][2 * HS];      // augmented [P | I] -> [I | Pinv]
    __shared__ float fS[HS];
    __shared__ float expD[HS];
    __shared__ float Psh[HS][HS];
    __shared__ float powS[NPOW][HS][HS]; // M^(2^k)
    __shared__ float x0S[HS];
    __shared__ float WmS[2][HS];
    __shared__ float bmS[2];

    const int tid  = threadIdx.x;
    const int lane = tid & 31;

    // ---- parallel phase: MLP hidden layer + small loads (all 256 threads)
    {
        const float t0 = target[0], t1 = target[1];
        h[tid] = fmaxf(fmaf(W1[2 * tid], t0, fmaf(W1[2 * tid + 1], t1, b1[tid])), 0.0f);
    }
    if (tid < 10)  expD[tid] = expf(D[tid]);
    if (tid >= 32 && tid < 132) {
        int q = tid - 32;
        Psh[q / 10][q % 10] = P[q];
    }
    if (tid >= 132 && tid < 152) (&WmS[0][0])[tid - 132] = Wm[tid - 132];
    if (tid == 152) bmS[0] = bm[0];
    if (tid == 153) bmS[1] = bm[1];
    __syncthreads();

    // ---- x0 partials: 10 outputs x 16 lanes
    if (tid < 160) {
        int o = tid >> 4, l = tid & 15;
        float s = 0.0f;
        #pragma unroll
        for (int j = 0; j < 16; j++)
            s = fmaf(W2[o * 256 + (l + 16 * j)], h[l + 16 * j], s);
        ps[o][l] = s;
    }
    __syncthreads();

    // =========== serial phase: warp 0 only, warp-synchronous ===========
    if (tid < 32) {
        // finalize x0
        if (lane < 10) {
            float s = b2[lane];
            #pragma unroll
            for (int l = 0; l < 16; l++) s += ps[lane][l];
            x0S[lane] = s;
        }
        // build augmented [P | I]
        #pragma unroll
        for (int idx = lane; idx < 200; idx += 32) {
            int r = idx / 20, c = idx % 20;
            B[r][c] = (c < 10) ? Psh[r][c] : ((c - 10) == r ? 1.0f : 0.0f);
        }
        __syncwarp();

        // Gauss-Jordan with partial pivoting
        for (int k = 0; k < 10; k++) {
            // argmax |B[r][k]| over r in [k,10): butterfly reduction
            float v = (lane >= k && lane < 10) ? fabsf(B[lane][k]) : -1.0f;
            int   p = lane;
            #pragma unroll
            for (int off = 16; off > 0; off >>= 1) {
                float ov = __shfl_xor_sync(0xffffffffu, v, off);
                int   op = __shfl_xor_sync(0xffffffffu, p, off);
                if (ov > v) { v = ov; p = op; }
            }
            // swap rows k and p
            if (p != k && lane < 20) {
                float tmp = B[k][lane];
                B[k][lane] = B[p][lane];
                B[p][lane] = tmp;
            }
            __syncwarp();
            const float pivinv = __frcp_rn(B[k][k]);
            __syncwarp();
            if (lane < 20) B[k][lane] *= pivinv;
            __syncwarp();
            if (lane == k) B[k][k] = 1.0f;
            if (lane < 10) fS[lane] = (lane == k) ? 0.0f : B[lane][k];
            __syncwarp();
            #pragma unroll
            for (int idx = lane; idx < 200; idx += 32) {
                int r = idx / 20, c = idx % 20;
                B[r][c] = fmaf(-fS[r], B[k][c], B[r][c]);
            }
            __syncwarp();
        }

        // M = I - 0.01 * (P * expD) @ Pinv   -> powS[0]
        #pragma unroll
        for (int idx = lane; idx < 100; idx += 32) {
            int i = idx / 10, j = idx % 10;
            float a = 0.0f;
            #pragma unroll
            for (int k = 0; k < 10; k++)
                a = fmaf(Psh[i][k] * expD[k], B[k][10 + j], a);
            powS[0][i][j] = ((i == j) ? 1.0f : 0.0f) - 0.01f * a;
        }
        __syncwarp();

        // repeated squaring: powS[k] = powS[k-1]^2
        for (int k = 1; k < NPOW; k++) {
            #pragma unroll
            for (int idx = lane; idx < 100; idx += 32) {
                int i = idx / 10, j = idx % 10;
                float a = 0.0f;
                #pragma unroll
                for (int q = 0; q < 10; q++)
                    a = fmaf(powS[k - 1][i][q], powS[k - 1][q][j], a);
                powS[k][i][j] = a;
            }
            __syncwarp();
        }
    }
    __syncthreads();

    // =========== rollout: one thread per timestep t ===========
    const int t = blockIdx.x * 256 + tid;  // 0..2047

    float x[HS];
    #pragma unroll
    for (int i = 0; i < HS; i++) x[i] = x0S[i];

    #pragma unroll
    for (int k = 0; k < NPOW; k++) {
        if ((t >> k) & 1) {
            float y[HS];
            #pragma unroll
            for (int i = 0; i < HS; i++) {
                float s = 0.0f;
                #pragma unroll
                for (int j = 0; j < HS; j++)
                    s = fmaf(powS[k][i][j], x[j], s);
                y[i] = s;
            }
            #pragma unroll
            for (int i = 0; i < HS; i++) x[i] = y[i];
        }
    }

    float a0 = bmS[0], a1 = bmS[1];
    #pragma unroll
    for (int j = 0; j < HS; j++) {
        a0 = fmaf(WmS[0][j], x[j], a0);
        a1 = fmaf(WmS[1][j], x[j], a1);
    }
    g_actions[2 * t]     = tanhf(a0) * 15000.0f;
    g_actions[2 * t + 1] = tanhf(a1) * 15000.0f;
}

// ---------------------------------------------------------------------------
// Kernel 2: streaming. out[g] = actions_scaled[g & 4095] + 150*eps[g]
// float4-vectorized, streaming cache hints (data touched exactly once),
// actions table staged in shared (1024 float4 = 16 KB).
// ---------------------------------------------------------------------------
__global__ void __launch_bounds__(256)
stream_kernel(const float4* __restrict__ eps4,
              float4* __restrict__ out4,
              int n4) {
    __shared__ float4 actS[1024];
    const int tid = threadIdx.x;
    const float4* act4 = reinterpret_cast<const float4*>(g_actions);
    for (int i = tid; i < 1024; i += 256) actS[i] = act4[i];
    __syncthreads();

    const int stride = gridDim.x * 256;
    int i = blockIdx.x * 256 + tid;
    #pragma unroll 4
    for (; i < n4; i += stride) {
        float4 e = __ldcs(&eps4[i]);
        float4 a = actS[i & 1023];
        float4 o;
        o.x = fmaf(150.0f, e.x, a.x);
        o.y = fmaf(150.0f, e.y, a.y);
        o.z = fmaf(150.0f, e.z, a.z);
        o.w = fmaf(150.0f, e.w, a.w);
        __stcs(&out4[i], o);
    }
}

// ---------------------------------------------------------------------------
extern "C" void kernel_launch(void* const* d_in, const int* in_sizes, int n_in,
                              void* d_out, int out_size) {
    const float* target = (const float*)d_in[0];
    const float* eps    = (const float*)d_in[1];
    const float* D      = (const float*)d_in[2];
    const float* P      = (const float*)d_in[3];
    const float* W1     = (const float*)d_in[4];
    const float* b1     = (const float*)d_in[5];
    const float* W2     = (const float*)d_in[6];
    const float* b2     = (const float*)d_in[7];
    const float* Wm     = (const float*)d_in[8];
    const float* bm     = (const float*)d_in[9];

    prep_kernel<<<N_STEPS / 256, 256>>>(target, D, P, W1, b1, W2, b2, Wm, bm);

    const int n4 = out_size / 4;  // 5,120,000 float4
    stream_kernel<<<1184, 256>>>((const float4*)eps, (float4*)d_out, n4);
}